// round 3
// baseline (speedup 1.0000x reference)
#include <cuda_runtime.h>
#include <cuda_bf16.h>
#include <math.h>

// Problem constants
static constexpr int   N_NODES = 200000;
static constexpr int   N_USERS = 100000;
static constexpr int   DIM     = 64;
static constexpr int   LAYERS  = 3;
static constexpr long  E_EDGES = 3000000;
static constexpr int   N_LINK  = 100000;
static constexpr int   EMB_COLS = (LAYERS + 1) * DIM; // 256

// ---------------------------------------------------------------------------
// Scratch (static device globals; no allocation allowed in kernel_launch)
// ---------------------------------------------------------------------------
__device__ float g_xt    [(size_t)N_NODES * DIM];       // current target_x (layers >= 1)
__device__ float g_aggs  [(size_t)N_NODES * DIM];       // source scatter accumulator
__device__ float g_aggt  [(size_t)N_NODES * DIM];       // target scatter accumulator
__device__ float g_invdeg_s[N_NODES];
__device__ float g_invdeg_t[N_NODES];
__device__ float g_embs  [(size_t)N_NODES * EMB_COLS];  // [N,256]: [emb | x1 | x2 | x3]

// ---------------------------------------------------------------------------
// Init: zero agg buffers + degree counters
// ---------------------------------------------------------------------------
__global__ void k_init() {
    long i = (long)blockIdx.x * blockDim.x + threadIdx.x;
    if (i < (long)N_NODES * DIM) {
        g_aggs[i] = 0.f;
        g_aggt[i] = 0.f;
    }
    if (i < N_NODES) {
        g_invdeg_s[i] = 0.f;
        g_invdeg_t[i] = 0.f;
    }
}

// Degree accumulation over both edge lists (same for all layers)
__global__ void k_deg(const int* __restrict__ s_dst, const int* __restrict__ t_dst) {
    long e = (long)blockIdx.x * blockDim.x + threadIdx.x;
    if (e < E_EDGES) {
        atomicAdd(&g_invdeg_s[s_dst[e]], 1.f);
        atomicAdd(&g_invdeg_t[t_dst[e]], 1.f);
    }
}

__global__ void k_inv() {
    int v = blockIdx.x * blockDim.x + threadIdx.x;
    if (v < N_NODES) {
        g_invdeg_s[v] = 1.f / fmaxf(g_invdeg_s[v], 1.f);
        g_invdeg_t[v] = 1.f / fmaxf(g_invdeg_t[v], 1.f);
    }
}

// Copy emb into column block 0 of the [N,256] embedding table
__global__ void k_copy_emb(const float* __restrict__ emb) {
    long i = (long)blockIdx.x * blockDim.x + threadIdx.x;
    if (i < (long)N_NODES * DIM) {
        long v = i >> 6;         // / 64
        int  d = (int)(i & 63);
        g_embs[v * EMB_COLS + d] = emb[i];
    }
}

// ---------------------------------------------------------------------------
// Scatter conv: 16 lanes per edge, float4 per lane.
// Covers BOTH graphs in one launch (tasks [0,E) = source, [E,2E) = target).
// Warp-uniform branches: warp spans exactly 2 edges of the same graph.
// ---------------------------------------------------------------------------
__global__ void k_scatter(const float* __restrict__ emb, int layer,
                          const int* __restrict__ s_src, const int* __restrict__ s_dst,
                          const int* __restrict__ t_src, const int* __restrict__ t_dst) {
    long tid  = (long)blockIdx.x * blockDim.x + threadIdx.x;
    long slot = tid >> 4;                 // edge slot (16 lanes each)
    if (slot >= 2L * E_EDGES) return;
    int chunk = (int)(tid & 15);          // which float4 of the 64-float row

    const float* xrow;
    float*       arow;
    if (slot < E_EDGES) {
        int e   = (int)slot;
        int src = __ldg(&s_src[e]);
        int dst = __ldg(&s_dst[e]);
        xrow = (layer == 0) ? (emb + (size_t)src * DIM)
                            : (g_embs + (size_t)src * EMB_COLS + (size_t)layer * DIM);
        arow = g_aggs + (size_t)dst * DIM;
    } else {
        int e   = (int)(slot - E_EDGES);
        int src = __ldg(&t_src[e]);
        int dst = __ldg(&t_dst[e]);
        xrow = ((layer == 0) ? emb : g_xt) + (size_t)src * DIM;
        arow = g_aggt + (size_t)dst * DIM;
    }

    float4 v = __ldg(reinterpret_cast<const float4*>(xrow) + chunk);
    // Vector reduction (sm_90+): 1 instruction instead of 4 scalar atomics.
    asm volatile("red.global.add.v4.f32 [%0], {%1,%2,%3,%4};"
                 :: "l"(arow + chunk * 4), "f"(v.x), "f"(v.y), "f"(v.z), "f"(v.w)
                 : "memory");
}

// ---------------------------------------------------------------------------
// Combine: per node compute means; for users apply the mix GEMM
//   ue = [ms|mt] @ W^T + b ; write source result into embs slice (layer+1)
// and target result into g_xt. Also re-zeros agg buffers for next layer.
// One warp per node; W transposed in smem (conflict-free).
// ---------------------------------------------------------------------------
__global__ void k_combine(const float* __restrict__ mix_w,
                          const float* __restrict__ mix_b, int layer) {
    __shared__ float WT[128 * 64];   // WT[k*64 + d] = W[d,k]   (32 KB)
    __shared__ float BB[64];

    const float* W = mix_w + (size_t)layer * 64 * 128;
    for (int i = threadIdx.x; i < 64 * 128; i += blockDim.x) {
        int k = i >> 6, d = i & 63;
        WT[i] = W[d * 128 + k];
    }
    if (threadIdx.x < 64) BB[threadIdx.x] = mix_b[layer * 64 + threadIdx.x];
    __syncthreads();

    int lane = threadIdx.x & 31;
    int warp = threadIdx.x >> 5;
    int wpb  = blockDim.x >> 5;

    for (int v = blockIdx.x * wpb + warp; v < N_NODES; v += gridDim.x * wpb) {
        float  is   = g_invdeg_s[v];
        float  it   = g_invdeg_t[v];
        size_t base = (size_t)v * DIM;

        float ms0 = g_aggs[base + lane]      * is;
        float ms1 = g_aggs[base + 32 + lane] * is;
        float mt0 = g_aggt[base + lane]      * it;
        float mt1 = g_aggt[base + 32 + lane] * it;

        // re-zero accumulators for the next layer
        g_aggs[base + lane] = 0.f;  g_aggs[base + 32 + lane] = 0.f;
        g_aggt[base + lane] = 0.f;  g_aggt[base + 32 + lane] = 0.f;

        float o0, o1, t0, t1;
        if (v < N_USERS) {
            float a0 = BB[lane], a1 = BB[lane + 32];
            #pragma unroll
            for (int k = 0; k < 32; k++) {
                float m = __shfl_sync(0xffffffffu, ms0, k);
                a0 += m * WT[k * 64 + lane];
                a1 += m * WT[k * 64 + lane + 32];
            }
            #pragma unroll
            for (int k = 0; k < 32; k++) {
                float m = __shfl_sync(0xffffffffu, ms1, k);
                a0 += m * WT[(k + 32) * 64 + lane];
                a1 += m * WT[(k + 32) * 64 + lane + 32];
            }
            #pragma unroll
            for (int k = 0; k < 32; k++) {
                float m = __shfl_sync(0xffffffffu, mt0, k);
                a0 += m * WT[(k + 64) * 64 + lane];
                a1 += m * WT[(k + 64) * 64 + lane + 32];
            }
            #pragma unroll
            for (int k = 0; k < 32; k++) {
                float m = __shfl_sync(0xffffffffu, mt1, k);
                a0 += m * WT[(k + 96) * 64 + lane];
                a1 += m * WT[(k + 96) * 64 + lane + 32];
            }
            o0 = a0; o1 = a1; t0 = a0; t1 = a1;   // users: both paths get user_emb
        } else {
            o0 = ms0; o1 = ms1; t0 = mt0; t1 = mt1;
        }

        g_xt[base + lane]      = t0;
        g_xt[base + 32 + lane] = t1;
        float* er = g_embs + (size_t)v * EMB_COLS + (size_t)(layer + 1) * DIM;
        er[lane]      = o0;
        er[lane + 32] = o1;
    }
}

// ---------------------------------------------------------------------------
// Prediction head: warp per link. dot([ue|ie], pred_w) + b -> leaky_relu -> sigmoid
// ---------------------------------------------------------------------------
__global__ void k_pred(const int* __restrict__ link,
                       const float* __restrict__ pred_w,
                       const float* __restrict__ pred_b,
                       float* __restrict__ out) {
    __shared__ float pw[512];
    for (int i = threadIdx.x; i < 512; i += blockDim.x) pw[i] = pred_w[i];
    __syncthreads();

    int lane = threadIdx.x & 31;
    int warp = threadIdx.x >> 5;
    int j = blockIdx.x * (blockDim.x >> 5) + warp;
    if (j >= N_LINK) return;

    int u  = __ldg(&link[j]);
    int it = __ldg(&link[N_LINK + j]);
    const float* ue = g_embs + (size_t)u  * EMB_COLS;
    const float* ie = g_embs + (size_t)it * EMB_COLS;

    float acc = 0.f;
    #pragma unroll
    for (int c = 0; c < 8; c++) acc += ue[lane + c * 32] * pw[lane + c * 32];
    #pragma unroll
    for (int c = 0; c < 8; c++) acc += ie[lane + c * 32] * pw[256 + lane + c * 32];

    #pragma unroll
    for (int o = 16; o > 0; o >>= 1) acc += __shfl_down_sync(0xffffffffu, acc, o);

    if (lane == 0) {
        float z = acc + pred_b[0];
        z = (z >= 0.f) ? z : 0.01f * z;          // leaky_relu(0.01)
        out[j] = 1.f / (1.f + expf(-z));         // sigmoid
    }
}

// ---------------------------------------------------------------------------
// Launch
// ---------------------------------------------------------------------------
extern "C" void kernel_launch(void* const* d_in, const int* in_sizes, int n_in,
                              void* d_out, int out_size) {
    const int*   sei    = (const int*)  d_in[0];   // [2,E] source graph
    const int*   tei    = (const int*)  d_in[1];   // [2,E] target graph
    const int*   link   = (const int*)  d_in[2];   // [2,NLINK]
    const float* emb    = (const float*)d_in[3];   // [N,64]
    const float* mix_w  = (const float*)d_in[4];   // [3,64,128]
    const float* mix_b  = (const float*)d_in[5];   // [3,64]
    const float* pred_w = (const float*)d_in[6];   // [1,512]
    const float* pred_b = (const float*)d_in[7];   // [1]
    float*       out    = (float*)d_out;           // [NLINK]

    const int* s_src = sei;
    const int* s_dst = sei + E_EDGES;
    const int* t_src = tei;
    const int* t_dst = tei + E_EDGES;

    const long ND = (long)N_NODES * DIM;

    k_init<<<(int)((ND + 255) / 256), 256>>>();
    k_deg <<<(int)((E_EDGES + 255) / 256), 256>>>(s_dst, t_dst);
    k_inv <<<(N_NODES + 255) / 256, 256>>>();
    k_copy_emb<<<(int)((ND + 255) / 256), 256>>>(emb);

    const long tasks = 2L * E_EDGES * 16;          // 16 lanes per edge, 2 graphs
    const int  scatter_blocks = (int)((tasks + 255) / 256);

    for (int l = 0; l < LAYERS; l++) {
        k_scatter<<<scatter_blocks, 256>>>(emb, l, s_src, s_dst, t_src, t_dst);
        k_combine<<<2960, 256>>>(mix_w, mix_b, l);
    }

    k_pred<<<(N_LINK + 7) / 8, 256>>>(link, pred_w, pred_b, out);
}

// round 4
// speedup vs baseline: 1.0016x; 1.0016x over previous
#include <cuda_runtime.h>
#include <cuda_bf16.h>
#include <math.h>

// Problem constants
static constexpr int   N_NODES = 200000;
static constexpr int   N_USERS = 100000;
static constexpr int   DIM     = 64;
static constexpr int   LAYERS  = 3;
static constexpr long  E_EDGES = 3000000;
static constexpr int   N_LINK  = 100000;
static constexpr int   EMB_COLS = (LAYERS + 1) * DIM; // 256

// ---------------------------------------------------------------------------
// Scratch (static device globals; no allocation allowed in kernel_launch)
// ---------------------------------------------------------------------------
__device__ float g_xt    [(size_t)N_NODES * DIM];       // current target_x (layers >= 1)
__device__ float g_aggs  [(size_t)N_NODES * DIM];       // source scatter accumulator
__device__ float g_aggt  [(size_t)N_NODES * DIM];       // target scatter accumulator
__device__ float g_invdeg_s[N_NODES];
__device__ float g_invdeg_t[N_NODES];
__device__ float g_embs  [(size_t)N_NODES * EMB_COLS];  // [N,256]: [emb | x1 | x2 | x3]

// ---------------------------------------------------------------------------
// Init: zero agg buffers + degree counters
// ---------------------------------------------------------------------------
__global__ void k_init() {
    long i = (long)blockIdx.x * blockDim.x + threadIdx.x;
    if (i < (long)N_NODES * DIM) {
        g_aggs[i] = 0.f;
        g_aggt[i] = 0.f;
    }
    if (i < N_NODES) {
        g_invdeg_s[i] = 0.f;
        g_invdeg_t[i] = 0.f;
    }
}

// Degree accumulation over both edge lists (same for all layers)
__global__ void k_deg(const int* __restrict__ s_dst, const int* __restrict__ t_dst) {
    long e = (long)blockIdx.x * blockDim.x + threadIdx.x;
    if (e < E_EDGES) {
        atomicAdd(&g_invdeg_s[s_dst[e]], 1.f);
        atomicAdd(&g_invdeg_t[t_dst[e]], 1.f);
    }
}

__global__ void k_inv() {
    int v = blockIdx.x * blockDim.x + threadIdx.x;
    if (v < N_NODES) {
        g_invdeg_s[v] = 1.f / fmaxf(g_invdeg_s[v], 1.f);
        g_invdeg_t[v] = 1.f / fmaxf(g_invdeg_t[v], 1.f);
    }
}

// Copy emb into column block 0 of the [N,256] embedding table
__global__ void k_copy_emb(const float* __restrict__ emb) {
    long i = (long)blockIdx.x * blockDim.x + threadIdx.x;
    if (i < (long)N_NODES * DIM) {
        long v = i >> 6;         // / 64
        int  d = (int)(i & 63);
        g_embs[v * EMB_COLS + d] = emb[i];
    }
}

// ---------------------------------------------------------------------------
// Scatter conv: 16 lanes per edge, float4 per lane.
// Covers BOTH graphs in one launch (tasks [0,E) = source, [E,2E) = target).
// Warp-uniform branches: warp spans exactly 2 edges of the same graph.
// ---------------------------------------------------------------------------
__global__ void k_scatter(const float* __restrict__ emb, int layer,
                          const int* __restrict__ s_src, const int* __restrict__ s_dst,
                          const int* __restrict__ t_src, const int* __restrict__ t_dst) {
    long tid  = (long)blockIdx.x * blockDim.x + threadIdx.x;
    long slot = tid >> 4;                 // edge slot (16 lanes each)
    if (slot >= 2L * E_EDGES) return;
    int chunk = (int)(tid & 15);          // which float4 of the 64-float row

    const float* xrow;
    float*       arow;
    if (slot < E_EDGES) {
        int e   = (int)slot;
        int src = __ldg(&s_src[e]);
        int dst = __ldg(&s_dst[e]);
        xrow = (layer == 0) ? (emb + (size_t)src * DIM)
                            : (g_embs + (size_t)src * EMB_COLS + (size_t)layer * DIM);
        arow = g_aggs + (size_t)dst * DIM;
    } else {
        int e   = (int)(slot - E_EDGES);
        int src = __ldg(&t_src[e]);
        int dst = __ldg(&t_dst[e]);
        xrow = ((layer == 0) ? emb : g_xt) + (size_t)src * DIM;
        arow = g_aggt + (size_t)dst * DIM;
    }

    float4 v = __ldg(reinterpret_cast<const float4*>(xrow) + chunk);
    // Vector reduction (sm_90+): 1 instruction instead of 4 scalar atomics.
    asm volatile("red.global.add.v4.f32 [%0], {%1,%2,%3,%4};"
                 :: "l"(arow + chunk * 4), "f"(v.x), "f"(v.y), "f"(v.z), "f"(v.w)
                 : "memory");
}

// ---------------------------------------------------------------------------
// Combine: per node compute means; for users apply the mix GEMM
//   ue = [ms|mt] @ W^T + b ; write source result into embs slice (layer+1)
// and target result into g_xt. Also re-zeros agg buffers for next layer.
// One warp per node; W transposed in smem (conflict-free).
// ---------------------------------------------------------------------------
__global__ void k_combine(const float* __restrict__ mix_w,
                          const float* __restrict__ mix_b, int layer) {
    __shared__ float WT[128 * 64];   // WT[k*64 + d] = W[d,k]   (32 KB)
    __shared__ float BB[64];

    const float* W = mix_w + (size_t)layer * 64 * 128;
    for (int i = threadIdx.x; i < 64 * 128; i += blockDim.x) {
        int k = i >> 6, d = i & 63;
        WT[i] = W[d * 128 + k];
    }
    if (threadIdx.x < 64) BB[threadIdx.x] = mix_b[layer * 64 + threadIdx.x];
    __syncthreads();

    int lane = threadIdx.x & 31;
    int warp = threadIdx.x >> 5;
    int wpb  = blockDim.x >> 5;

    for (int v = blockIdx.x * wpb + warp; v < N_NODES; v += gridDim.x * wpb) {
        float  is   = g_invdeg_s[v];
        float  it   = g_invdeg_t[v];
        size_t base = (size_t)v * DIM;

        float ms0 = g_aggs[base + lane]      * is;
        float ms1 = g_aggs[base + 32 + lane] * is;
        float mt0 = g_aggt[base + lane]      * it;
        float mt1 = g_aggt[base + 32 + lane] * it;

        // re-zero accumulators for the next layer
        g_aggs[base + lane] = 0.f;  g_aggs[base + 32 + lane] = 0.f;
        g_aggt[base + lane] = 0.f;  g_aggt[base + 32 + lane] = 0.f;

        float o0, o1, t0, t1;
        if (v < N_USERS) {
            float a0 = BB[lane], a1 = BB[lane + 32];
            #pragma unroll
            for (int k = 0; k < 32; k++) {
                float m = __shfl_sync(0xffffffffu, ms0, k);
                a0 += m * WT[k * 64 + lane];
                a1 += m * WT[k * 64 + lane + 32];
            }
            #pragma unroll
            for (int k = 0; k < 32; k++) {
                float m = __shfl_sync(0xffffffffu, ms1, k);
                a0 += m * WT[(k + 32) * 64 + lane];
                a1 += m * WT[(k + 32) * 64 + lane + 32];
            }
            #pragma unroll
            for (int k = 0; k < 32; k++) {
                float m = __shfl_sync(0xffffffffu, mt0, k);
                a0 += m * WT[(k + 64) * 64 + lane];
                a1 += m * WT[(k + 64) * 64 + lane + 32];
            }
            #pragma unroll
            for (int k = 0; k < 32; k++) {
                float m = __shfl_sync(0xffffffffu, mt1, k);
                a0 += m * WT[(k + 96) * 64 + lane];
                a1 += m * WT[(k + 96) * 64 + lane + 32];
            }
            o0 = a0; o1 = a1; t0 = a0; t1 = a1;   // users: both paths get user_emb
        } else {
            o0 = ms0; o1 = ms1; t0 = mt0; t1 = mt1;
        }

        g_xt[base + lane]      = t0;
        g_xt[base + 32 + lane] = t1;
        float* er = g_embs + (size_t)v * EMB_COLS + (size_t)(layer + 1) * DIM;
        er[lane]      = o0;
        er[lane + 32] = o1;
    }
}

// ---------------------------------------------------------------------------
// Prediction head: warp per link. dot([ue|ie], pred_w) + b -> leaky_relu -> sigmoid
// ---------------------------------------------------------------------------
__global__ void k_pred(const int* __restrict__ link,
                       const float* __restrict__ pred_w,
                       const float* __restrict__ pred_b,
                       float* __restrict__ out) {
    __shared__ float pw[512];
    for (int i = threadIdx.x; i < 512; i += blockDim.x) pw[i] = pred_w[i];
    __syncthreads();

    int lane = threadIdx.x & 31;
    int warp = threadIdx.x >> 5;
    int j = blockIdx.x * (blockDim.x >> 5) + warp;
    if (j >= N_LINK) return;

    int u  = __ldg(&link[j]);
    int it = __ldg(&link[N_LINK + j]);
    const float* ue = g_embs + (size_t)u  * EMB_COLS;
    const float* ie = g_embs + (size_t)it * EMB_COLS;

    float acc = 0.f;
    #pragma unroll
    for (int c = 0; c < 8; c++) acc += ue[lane + c * 32] * pw[lane + c * 32];
    #pragma unroll
    for (int c = 0; c < 8; c++) acc += ie[lane + c * 32] * pw[256 + lane + c * 32];

    #pragma unroll
    for (int o = 16; o > 0; o >>= 1) acc += __shfl_down_sync(0xffffffffu, acc, o);

    if (lane == 0) {
        float z = acc + pred_b[0];
        z = (z >= 0.f) ? z : 0.01f * z;          // leaky_relu(0.01)
        out[j] = 1.f / (1.f + expf(-z));         // sigmoid
    }
}

// ---------------------------------------------------------------------------
// Launch
// ---------------------------------------------------------------------------
extern "C" void kernel_launch(void* const* d_in, const int* in_sizes, int n_in,
                              void* d_out, int out_size) {
    const int*   sei    = (const int*)  d_in[0];   // [2,E] source graph
    const int*   tei    = (const int*)  d_in[1];   // [2,E] target graph
    const int*   link   = (const int*)  d_in[2];   // [2,NLINK]
    const float* emb    = (const float*)d_in[3];   // [N,64]
    const float* mix_w  = (const float*)d_in[4];   // [3,64,128]
    const float* mix_b  = (const float*)d_in[5];   // [3,64]
    const float* pred_w = (const float*)d_in[6];   // [1,512]
    const float* pred_b = (const float*)d_in[7];   // [1]
    float*       out    = (float*)d_out;           // [NLINK]

    const int* s_src = sei;
    const int* s_dst = sei + E_EDGES;
    const int* t_src = tei;
    const int* t_dst = tei + E_EDGES;

    const long ND = (long)N_NODES * DIM;

    k_init<<<(int)((ND + 255) / 256), 256>>>();
    k_deg <<<(int)((E_EDGES + 255) / 256), 256>>>(s_dst, t_dst);
    k_inv <<<(N_NODES + 255) / 256, 256>>>();
    k_copy_emb<<<(int)((ND + 255) / 256), 256>>>(emb);

    const long tasks = 2L * E_EDGES * 16;          // 16 lanes per edge, 2 graphs
    const int  scatter_blocks = (int)((tasks + 255) / 256);

    for (int l = 0; l < LAYERS; l++) {
        k_scatter<<<scatter_blocks, 256>>>(emb, l, s_src, s_dst, t_src, t_dst);
        k_combine<<<2960, 256>>>(mix_w, mix_b, l);
    }

    k_pred<<<(N_LINK + 7) / 8, 256>>>(link, pred_w, pred_b, out);
}

// round 5
// speedup vs baseline: 1.0791x; 1.0774x over previous
#include <cuda_runtime.h>
#include <cuda_bf16.h>
#include <math.h>

// Problem constants
static constexpr int   N_NODES  = 200000;
static constexpr int   N_USERS  = 100000;
static constexpr int   DIM      = 64;
static constexpr int   LAYERS   = 3;
static constexpr long  E_EDGES  = 3000000;
static constexpr int   N_LINK   = 100000;
static constexpr int   EMB_COLS = (LAYERS + 1) * DIM;          // 256
static constexpr int   NB_SCAN  = (N_NODES + 1023) / 1024;     // 196

// ---------------------------------------------------------------------------
// Scratch (static device globals; no allocation allowed in kernel_launch)
// ---------------------------------------------------------------------------
__device__ int   g_deg_s[N_NODES],  g_deg_t[N_NODES];
__device__ int   g_row_s[N_NODES],  g_row_t[N_NODES];     // exclusive prefix (CSR rowptr)
__device__ int   g_cur_s[N_NODES],  g_cur_t[N_NODES];     // fill cursors
__device__ int   g_csr_s[E_EDGES],  g_csr_t[E_EDGES];     // neighbor (src) lists per dst
__device__ int   g_ps_s[256],       g_ps_t[256];          // scan partials
__device__ float g_invdeg_s[N_NODES], g_invdeg_t[N_NODES];
__device__ float g_means[(size_t)N_NODES * DIM];          // source-graph means
__device__ float g_meant[(size_t)N_NODES * DIM];          // target-graph means
__device__ float g_xt   [(size_t)N_NODES * DIM];          // target_x for next layer
__device__ float g_embs [(size_t)N_NODES * EMB_COLS];     // [N,256]: [emb|x1|x2|x3]

// ---------------------------------------------------------------------------
// CSR build: zero -> histogram -> 2-level exclusive scan -> cursor fill
// ---------------------------------------------------------------------------
__global__ void k_zero_deg() {
    int i = blockIdx.x * blockDim.x + threadIdx.x;
    if (i < N_NODES) { g_deg_s[i] = 0; g_deg_t[i] = 0; }
}

__global__ void k_hist(const int* __restrict__ s_dst, const int* __restrict__ t_dst) {
    long e = (long)blockIdx.x * blockDim.x + threadIdx.x;
    if (e < E_EDGES) {
        atomicAdd(&g_deg_s[s_dst[e]], 1);
        atomicAdd(&g_deg_t[t_dst[e]], 1);
    }
}

// Per-1024-chunk exclusive scan; blockIdx.y selects graph (0=source, 1=target)
__global__ void k_scan1() {
    __shared__ int sh[1024];
    const int* deg = blockIdx.y ? g_deg_t : g_deg_s;
    int*       row = blockIdx.y ? g_row_t : g_row_s;
    int*       ps  = blockIdx.y ? g_ps_t  : g_ps_s;

    int i = blockIdx.x * 1024 + threadIdx.x;
    int v = (i < N_NODES) ? deg[i] : 0;
    sh[threadIdx.x] = v;
    __syncthreads();
    #pragma unroll
    for (int off = 1; off < 1024; off <<= 1) {
        int t = (threadIdx.x >= off) ? sh[threadIdx.x - off] : 0;
        __syncthreads();
        sh[threadIdx.x] += t;
        __syncthreads();
    }
    if (i < N_NODES) row[i] = sh[threadIdx.x] - v;        // exclusive
    if (threadIdx.x == 1023) ps[blockIdx.x] = sh[1023];
}

// Scan the (<=256) block partials for both graphs
__global__ void k_scan2() {
    __shared__ int sh[256];
    int t = threadIdx.x;

    int v = (t < NB_SCAN) ? g_ps_s[t] : 0;
    sh[t] = v; __syncthreads();
    #pragma unroll
    for (int off = 1; off < 256; off <<= 1) {
        int u = (t >= off) ? sh[t - off] : 0;
        __syncthreads(); sh[t] += u; __syncthreads();
    }
    if (t < NB_SCAN) g_ps_s[t] = sh[t] - v;
    __syncthreads();

    v = (t < NB_SCAN) ? g_ps_t[t] : 0;
    sh[t] = v; __syncthreads();
    #pragma unroll
    for (int off = 1; off < 256; off <<= 1) {
        int u = (t >= off) ? sh[t - off] : 0;
        __syncthreads(); sh[t] += u; __syncthreads();
    }
    if (t < NB_SCAN) g_ps_t[t] = sh[t] - v;
}

// Apply block offsets; init cursors; compute reciprocal degrees
__global__ void k_scan3() {
    int i = blockIdx.x * blockDim.x + threadIdx.x;
    if (i >= N_NODES) return;
    int b = i >> 10;
    int rs = g_row_s[i] + g_ps_s[b];
    int rt = g_row_t[i] + g_ps_t[b];
    g_row_s[i] = rs;  g_cur_s[i] = rs;
    g_row_t[i] = rt;  g_cur_t[i] = rt;
    g_invdeg_s[i] = 1.f / fmaxf((float)g_deg_s[i], 1.f);
    g_invdeg_t[i] = 1.f / fmaxf((float)g_deg_t[i], 1.f);
}

__global__ void k_fill(const int* __restrict__ s_src, const int* __restrict__ s_dst,
                       const int* __restrict__ t_src, const int* __restrict__ t_dst) {
    long e = (long)blockIdx.x * blockDim.x + threadIdx.x;
    if (e < E_EDGES) {
        int ps = atomicAdd(&g_cur_s[s_dst[e]], 1);
        g_csr_s[ps] = s_src[e];
        int pt = atomicAdd(&g_cur_t[t_dst[e]], 1);
        g_csr_t[pt] = t_src[e];
    }
}

// ---------------------------------------------------------------------------
// Copy emb (vectorized) into column block 0 of the [N,256] embedding table
// ---------------------------------------------------------------------------
__global__ void k_copy_emb(const float4* __restrict__ emb4) {
    long i = (long)blockIdx.x * blockDim.x + threadIdx.x;     // N*16 float4s
    if (i < (long)N_NODES * (DIM / 4)) {
        long v = i >> 4;           // / 16
        int  d = (int)(i & 15);
        reinterpret_cast<float4*>(g_embs)[v * (EMB_COLS / 4) + d] = emb4[i];
    }
}

// ---------------------------------------------------------------------------
// Gather conv: one warp per destination node. Batch 32 neighbor indices,
// shfl-broadcast, accumulate 256B rows (float2/lane). Writes pre-scaled mean.
// No atomics, no zeroing.
// ---------------------------------------------------------------------------
__global__ void __launch_bounds__(256)
k_conv(const float* __restrict__ x, int xstride,
       const int* __restrict__ rowptr, const int* __restrict__ deg,
       const float* __restrict__ invdeg, const int* __restrict__ csr,
       float* __restrict__ outmean) {
    int warp = (blockIdx.x * blockDim.x + threadIdx.x) >> 5;
    int lane = threadIdx.x & 31;
    if (warp >= N_NODES) return;

    int start = rowptr[warp];
    int d     = deg[warp];

    float a0 = 0.f, a1 = 0.f;
    for (int j0 = 0; j0 < d; j0 += 32) {
        int myidx = (j0 + lane < d) ? __ldg(&csr[start + j0 + lane]) : 0;
        int m = min(32, d - j0);
        for (int j = 0; j < m; j++) {
            int s = __shfl_sync(0xffffffffu, myidx, j);
            float2 v = __ldg(reinterpret_cast<const float2*>(
                                 x + (size_t)s * xstride) + lane);
            a0 += v.x;
            a1 += v.y;
        }
    }
    float iv = invdeg[warp];
    float2 o; o.x = a0 * iv; o.y = a1 * iv;
    *reinterpret_cast<float2*>(outmean + (size_t)warp * DIM + 2 * lane) = o;
}

// ---------------------------------------------------------------------------
// Combine: users get mix GEMM ue=[ms|mt]@W^T+b; write source slice into
// g_embs(layer+1) and target into g_xt. One warp per node; WT in smem.
// ---------------------------------------------------------------------------
__global__ void __launch_bounds__(256)
k_combine(const float* __restrict__ mix_w, const float* __restrict__ mix_b, int layer) {
    __shared__ float WT[128 * 64];   // WT[k*64 + d] = W[d,k]   (32 KB)
    __shared__ float BB[64];

    const float* W = mix_w + (size_t)layer * 64 * 128;
    for (int i = threadIdx.x; i < 64 * 128; i += blockDim.x) {
        int k = i >> 6, d = i & 63;
        WT[i] = W[d * 128 + k];
    }
    if (threadIdx.x < 64) BB[threadIdx.x] = mix_b[layer * 64 + threadIdx.x];
    __syncthreads();

    int lane = threadIdx.x & 31;
    int warp = threadIdx.x >> 5;
    int wpb  = blockDim.x >> 5;

    for (int v = blockIdx.x * wpb + warp; v < N_NODES; v += gridDim.x * wpb) {
        size_t base = (size_t)v * DIM;

        float ms0 = g_means[base + lane];
        float ms1 = g_means[base + 32 + lane];
        float mt0 = g_meant[base + lane];
        float mt1 = g_meant[base + 32 + lane];

        float o0, o1, t0, t1;
        if (v < N_USERS) {
            float a0 = BB[lane], a1 = BB[lane + 32];
            #pragma unroll
            for (int k = 0; k < 32; k++) {
                float m = __shfl_sync(0xffffffffu, ms0, k);
                a0 += m * WT[k * 64 + lane];
                a1 += m * WT[k * 64 + lane + 32];
            }
            #pragma unroll
            for (int k = 0; k < 32; k++) {
                float m = __shfl_sync(0xffffffffu, ms1, k);
                a0 += m * WT[(k + 32) * 64 + lane];
                a1 += m * WT[(k + 32) * 64 + lane + 32];
            }
            #pragma unroll
            for (int k = 0; k < 32; k++) {
                float m = __shfl_sync(0xffffffffu, mt0, k);
                a0 += m * WT[(k + 64) * 64 + lane];
                a1 += m * WT[(k + 64) * 64 + lane + 32];
            }
            #pragma unroll
            for (int k = 0; k < 32; k++) {
                float m = __shfl_sync(0xffffffffu, mt1, k);
                a0 += m * WT[(k + 96) * 64 + lane];
                a1 += m * WT[(k + 96) * 64 + lane + 32];
            }
            o0 = a0; o1 = a1; t0 = a0; t1 = a1;   // users: both paths get user_emb
        } else {
            o0 = ms0; o1 = ms1; t0 = mt0; t1 = mt1;
        }

        g_xt[base + lane]      = t0;
        g_xt[base + 32 + lane] = t1;
        float* er = g_embs + (size_t)v * EMB_COLS + (size_t)(layer + 1) * DIM;
        er[lane]      = o0;
        er[lane + 32] = o1;
    }
}

// ---------------------------------------------------------------------------
// Prediction head: warp per link. dot([ue|ie], pred_w)+b -> leaky_relu -> sigmoid
// ---------------------------------------------------------------------------
__global__ void k_pred(const int* __restrict__ link,
                       const float* __restrict__ pred_w,
                       const float* __restrict__ pred_b,
                       float* __restrict__ out) {
    __shared__ float pw[512];
    for (int i = threadIdx.x; i < 512; i += blockDim.x) pw[i] = pred_w[i];
    __syncthreads();

    int lane = threadIdx.x & 31;
    int warp = threadIdx.x >> 5;
    int j = blockIdx.x * (blockDim.x >> 5) + warp;
    if (j >= N_LINK) return;

    int u  = __ldg(&link[j]);
    int it = __ldg(&link[N_LINK + j]);
    const float* ue = g_embs + (size_t)u  * EMB_COLS;
    const float* ie = g_embs + (size_t)it * EMB_COLS;

    float acc = 0.f;
    #pragma unroll
    for (int c = 0; c < 8; c++) acc += ue[lane + c * 32] * pw[lane + c * 32];
    #pragma unroll
    for (int c = 0; c < 8; c++) acc += ie[lane + c * 32] * pw[256 + lane + c * 32];

    #pragma unroll
    for (int o = 16; o > 0; o >>= 1) acc += __shfl_down_sync(0xffffffffu, acc, o);

    if (lane == 0) {
        float z = acc + pred_b[0];
        z = (z >= 0.f) ? z : 0.01f * z;          // leaky_relu(0.01)
        out[j] = 1.f / (1.f + expf(-z));         // sigmoid
    }
}

// ---------------------------------------------------------------------------
// Launch
// ---------------------------------------------------------------------------
extern "C" void kernel_launch(void* const* d_in, const int* in_sizes, int n_in,
                              void* d_out, int out_size) {
    const int*   sei    = (const int*)  d_in[0];   // [2,E] source graph
    const int*   tei    = (const int*)  d_in[1];   // [2,E] target graph
    const int*   link   = (const int*)  d_in[2];   // [2,NLINK]
    const float* emb    = (const float*)d_in[3];   // [N,64]
    const float* mix_w  = (const float*)d_in[4];   // [3,64,128]
    const float* mix_b  = (const float*)d_in[5];   // [3,64]
    const float* pred_w = (const float*)d_in[6];   // [1,512]
    const float* pred_b = (const float*)d_in[7];   // [1]
    float*       out    = (float*)d_out;           // [NLINK]

    const int* s_src = sei;
    const int* s_dst = sei + E_EDGES;
    const int* t_src = tei;
    const int* t_dst = tei + E_EDGES;

    // ---- CSR build (edge lists are layer-invariant) ----
    k_zero_deg<<<(N_NODES + 255) / 256, 256>>>();
    k_hist<<<(int)((E_EDGES + 255) / 256), 256>>>(s_dst, t_dst);
    k_scan1<<<dim3(NB_SCAN, 2), 1024>>>();
    k_scan2<<<1, 256>>>();
    k_scan3<<<(N_NODES + 255) / 256, 256>>>();
    k_fill<<<(int)((E_EDGES + 255) / 256), 256>>>(s_src, s_dst, t_src, t_dst);

    k_copy_emb<<<(int)(((long)N_NODES * 16 + 255) / 256), 256>>>(
        reinterpret_cast<const float4*>(emb));

    const int conv_blocks = (N_NODES * 32 + 255) / 256;   // warp per node

    for (int l = 0; l < LAYERS; l++) {
        // source graph conv
        const float* xs = (l == 0) ? emb : (g_embs + (size_t)l * DIM);
        int xs_stride   = (l == 0) ? DIM : EMB_COLS;
        k_conv<<<conv_blocks, 256>>>(xs, xs_stride, g_row_s, g_deg_s,
                                     g_invdeg_s, g_csr_s, g_means);
        // target graph conv
        const float* xtp = (l == 0) ? emb : g_xt;
        k_conv<<<conv_blocks, 256>>>(xtp, DIM, g_row_t, g_deg_t,
                                     g_invdeg_t, g_csr_t, g_meant);

        k_combine<<<2960, 256>>>(mix_w, mix_b, l);
    }

    k_pred<<<(N_LINK + 7) / 8, 256>>>(link, pred_w, pred_b, out);
}